// round 15
// baseline (speedup 1.0000x reference)
#include <cuda_runtime.h>
#include <cuda_bf16.h>

// db4 level-1 DWT low-pass reconstruction. 8 contiguous floats per thread via
// Blackwell 256-bit vector ld/st, distance-1 shuffle halos. Cross-warp halos
// staged through 768B of shared memory (no edge global loads at all); row-end
// symmetric reflection comes from the boundary thread's OWN registers.
// x: [8192 rows, 4096] fp32. out = low (N floats) then high (N floats).
//
//   ca[K]     = sum_{m=0..7} h[m] * X(2K+1-m)     (X = symmetric-ext x)
//   low[2K]   = h1*ca[K] + h3*ca[K+1] + h5*ca[K+2] + h7*ca[K+3]
//   low[2K+1] = h0*ca[K] + h2*ca[K+1] + h4*ca[K+2] + h6*ca[K+3]
//   high      = x - low
//
// Thread t (256/CTA), group g in {0,1}: owns float8 E = 256*g + t ->
// outputs x[8E .. 8E+7]. Window w[0..19] = X(8E-6 .. 8E+13):
//   w6..w13  = own float8 (one LDG.256)
//   w0..w5   = lane t-1 floats 2..7  (shfl_up 1)   [warp-interior]
//   w14..w19 = lane t+1 floats 0..5  (shfl_down 1) [warp-interior]
// Warp-boundary lanes read the neighbor warp's staged boundary floats from
// shared memory (linear warp index W = 8g + warpid, 16 warps-slots).

#define ROW_L    4096
#define NTHREADS 256
#define NF8      (ROW_L / 8)     // 512 float8 per row
#define NWSLOT   16              // 2 groups x 8 warps

struct F8 { float v[8]; };

__device__ __forceinline__ F8 ldg256(const float* p) {
    F8 r;
    asm("ld.global.nc.v8.f32 {%0,%1,%2,%3,%4,%5,%6,%7}, [%8];"
        : "=f"(r.v[0]), "=f"(r.v[1]), "=f"(r.v[2]), "=f"(r.v[3]),
          "=f"(r.v[4]), "=f"(r.v[5]), "=f"(r.v[6]), "=f"(r.v[7])
        : "l"(p));
    return r;
}

__device__ __forceinline__ void stg256(float* p,
                                       float a0, float a1, float a2, float a3,
                                       float a4, float a5, float a6, float a7) {
    asm volatile("st.global.v8.f32 [%0], {%1,%2,%3,%4,%5,%6,%7,%8};"
        :: "l"(p), "f"(a0), "f"(a1), "f"(a2), "f"(a3),
           "f"(a4), "f"(a5), "f"(a6), "f"(a7)
        : "memory");
}

__global__ void __launch_bounds__(NTHREADS)
dwt_db4_kernel(const float* __restrict__ x,
               float* __restrict__ low_out,
               float* __restrict__ high_out)
{
    // sb[W][0..5]  = head floats x[8E..8E+5]   of warp W's lane 0
    // sb[W][6..11] = tail floats x[8E+2..8E+7] of warp W's lane 31
    __shared__ float sb[NWSLOT][12];

    const float h0 = -0.010597401784997278f;
    const float h1 =  0.032883011666982945f;
    const float h2 =  0.030841381835986965f;
    const float h3 = -0.18703481171888114f;
    const float h4 = -0.02798376941698385f;
    const float h5 =  0.6308807679295904f;
    const float h6 =  0.7148465705525415f;
    const float h7 =  0.23037781330885523f;

    const int t = threadIdx.x;
    const int l = t & 31;
    const int wid = t >> 5;              // warp in CTA, 0..7
    const size_t row = blockIdx.x;
    const float* __restrict__ xr = x + row * (size_t)ROW_L;
    float* __restrict__ lowp  = low_out  + row * (size_t)ROW_L;
    float* __restrict__ highp = high_out + row * (size_t)ROW_L;

    // Front-batched main loads: 2 x LDG.256 (64B per thread in flight)
    F8 va[2];
    #pragma unroll
    for (int g = 0; g < 2; ++g)
        va[g] = ldg256(xr + (size_t)(g * NTHREADS + t) * 8);

    // Stage warp-boundary floats for both groups, one barrier
    #pragma unroll
    for (int g = 0; g < 2; ++g) {
        const int W = g * 8 + wid;
        if (l == 0) {
            #pragma unroll
            for (int i = 0; i < 6; ++i) sb[W][i] = va[g].v[i];
        }
        if (l == 31) {
            #pragma unroll
            for (int i = 0; i < 6; ++i) sb[W][6 + i] = va[g].v[2 + i];
        }
    }
    __syncthreads();

    #pragma unroll
    for (int g = 0; g < 2; ++g) {
        const int E = g * NTHREADS + t;      // float8 index in row, 0..511
        const int W = g * 8 + wid;           // linear warp slot, 0..15
        const F8 v = va[g];

        // window w[i] = X(8E - 6 + i), i = 0..19
        float w0, w1, w2, w3, w4, w5;
        const float w6 = v.v[0], w7 = v.v[1], w8 = v.v[2], w9 = v.v[3];
        const float w10 = v.v[4], w11 = v.v[5], w12 = v.v[6], w13 = v.v[7];
        float w14, w15, w16, w17, w18, w19;

        // halos via distance-1 shuffle (full-warp convergent)
        w0  = __shfl_up_sync(0xffffffffu, v.v[2], 1);
        w1  = __shfl_up_sync(0xffffffffu, v.v[3], 1);
        w2  = __shfl_up_sync(0xffffffffu, v.v[4], 1);
        w3  = __shfl_up_sync(0xffffffffu, v.v[5], 1);
        w4  = __shfl_up_sync(0xffffffffu, v.v[6], 1);
        w5  = __shfl_up_sync(0xffffffffu, v.v[7], 1);
        w14 = __shfl_down_sync(0xffffffffu, v.v[0], 1);
        w15 = __shfl_down_sync(0xffffffffu, v.v[1], 1);
        w16 = __shfl_down_sync(0xffffffffu, v.v[2], 1);
        w17 = __shfl_down_sync(0xffffffffu, v.v[3], 1);
        w18 = __shfl_down_sync(0xffffffffu, v.v[4], 1);
        w19 = __shfl_down_sync(0xffffffffu, v.v[5], 1);

        // warp-boundary fixups: shared (interior) or own-register reflection
        if (l == 0) {
            if (W == 0) {
                // X(-6..-1) = x[5..0] = own v[5..0] reversed
                w0 = v.v[5]; w1 = v.v[4]; w2 = v.v[3];
                w3 = v.v[2]; w4 = v.v[1]; w5 = v.v[0];
            } else {
                w0 = sb[W - 1][6];  w1 = sb[W - 1][7];  w2 = sb[W - 1][8];
                w3 = sb[W - 1][9];  w4 = sb[W - 1][10]; w5 = sb[W - 1][11];
            }
        }
        if (l == 31) {
            if (W == NWSLOT - 1) {
                // X(4096..4101) = x[4095..4090] = own v[7..2] reversed
                w14 = v.v[7]; w15 = v.v[6]; w16 = v.v[5];
                w17 = v.v[4]; w18 = v.v[3]; w19 = v.v[2];
            } else {
                w14 = sb[W + 1][0]; w15 = sb[W + 1][1]; w16 = sb[W + 1][2];
                w17 = sb[W + 1][3]; w18 = sb[W + 1][4]; w19 = sb[W + 1][5];
            }
        }

        // analysis: ca[j] (global coeff index 4E + j), j = 0..6
        // ca_j = sum_m h[m] * w[2j + 7 - m]
        const float wv[20] = { w0, w1, w2, w3, w4, w5, w6, w7, w8, w9,
                               w10, w11, w12, w13, w14, w15, w16, w17, w18, w19 };
        float ca[7];
        #pragma unroll
        for (int j = 0; j < 7; ++j) {
            float s;
            s = h0 * wv[2 * j + 7];
            s = fmaf(h1, wv[2 * j + 6], s);
            s = fmaf(h2, wv[2 * j + 5], s);
            s = fmaf(h3, wv[2 * j + 4], s);
            s = fmaf(h4, wv[2 * j + 3], s);
            s = fmaf(h5, wv[2 * j + 2], s);
            s = fmaf(h6, wv[2 * j + 1], s);
            s = fmaf(h7, wv[2 * j + 0], s);
            ca[j] = s;
        }

        // synthesis: pairs p = 0..3 -> outputs x[8E .. 8E+7]
        float le[4], lo[4];
        #pragma unroll
        for (int p = 0; p < 4; ++p) {
            float e;
            e = h1 * ca[p];
            e = fmaf(h3, ca[p + 1], e);
            e = fmaf(h5, ca[p + 2], e);
            e = fmaf(h7, ca[p + 3], e);
            le[p] = e;

            float o;
            o = h0 * ca[p];
            o = fmaf(h2, ca[p + 1], o);
            o = fmaf(h4, ca[p + 2], o);
            o = fmaf(h6, ca[p + 3], o);
            lo[p] = o;
        }

        stg256(lowp + (size_t)E * 8,
               le[0], lo[0], le[1], lo[1], le[2], lo[2], le[3], lo[3]);
        stg256(highp + (size_t)E * 8,
               w6 - le[0], w7 - lo[0], w8 - le[1], w9 - lo[1],
               w10 - le[2], w11 - lo[2], w12 - le[3], w13 - lo[3]);
    }
}

extern "C" void kernel_launch(void* const* d_in, const int* in_sizes, int n_in,
                              void* d_out, int out_size)
{
    const float* x = (const float*)d_in[0];
    const int n = in_sizes[0];            // 16*512*4096
    float* low  = (float*)d_out;          // outputs concatenated: (low, high)
    float* high = low + (size_t)n;
    const int rows = n / ROW_L;           // 8192
    dwt_db4_kernel<<<rows, NTHREADS>>>(x, low, high);
}

// round 16
// speedup vs baseline: 1.0056x; 1.0056x over previous
#include <cuda_runtime.h>
#include <cuda_bf16.h>

// db4 level-1 DWT low-pass reconstruction. 8 contiguous floats per thread via
// Blackwell 256-bit vector ld/st, distance-1 shuffle halos. Cross-warp halos
// staged through 768B of shared memory (no edge global loads); row-end
// symmetric reflection from the boundary thread's OWN registers. Pure
// streaming: loads are .cs (read-once, evict-first), input never re-read.
// x: [8192 rows, 4096] fp32. out = low (N floats) then high (N floats).
//
//   ca[K]     = sum_{m=0..7} h[m] * X(2K+1-m)     (X = symmetric-ext x)
//   low[2K]   = h1*ca[K] + h3*ca[K+1] + h5*ca[K+2] + h7*ca[K+3]
//   low[2K+1] = h0*ca[K] + h2*ca[K+1] + h4*ca[K+2] + h6*ca[K+3]
//   high      = x - low
//
// Thread t (256/CTA), group g in {0,1}: owns float8 E = 256*g + t ->
// outputs x[8E .. 8E+7]. Window w[0..19] = X(8E-6 .. 8E+13):
//   w6..w13  = own float8 (one LDG.256)
//   w0..w5   = lane t-1 floats 2..7  (shfl_up 1)   [warp-interior]
//   w14..w19 = lane t+1 floats 0..5  (shfl_down 1) [warp-interior]
// Warp-boundary lanes read the neighbor warp's staged boundary floats from
// shared memory (linear warp slot W = 8g + warpid, 16 slots).

#define ROW_L    4096
#define NTHREADS 256
#define NF8      (ROW_L / 8)     // 512 float8 per row
#define NWSLOT   16              // 2 groups x 8 warps

struct F8 { float v[8]; };

__device__ __forceinline__ F8 ldg256cs(const float* p) {
    F8 r;
    asm("ld.global.nc.cs.v8.f32 {%0,%1,%2,%3,%4,%5,%6,%7}, [%8];"
        : "=f"(r.v[0]), "=f"(r.v[1]), "=f"(r.v[2]), "=f"(r.v[3]),
          "=f"(r.v[4]), "=f"(r.v[5]), "=f"(r.v[6]), "=f"(r.v[7])
        : "l"(p));
    return r;
}

__device__ __forceinline__ void stg256(float* p,
                                       float a0, float a1, float a2, float a3,
                                       float a4, float a5, float a6, float a7) {
    asm volatile("st.global.v8.f32 [%0], {%1,%2,%3,%4,%5,%6,%7,%8};"
        :: "l"(p), "f"(a0), "f"(a1), "f"(a2), "f"(a3),
           "f"(a4), "f"(a5), "f"(a6), "f"(a7)
        : "memory");
}

__global__ void __launch_bounds__(NTHREADS)
dwt_db4_kernel(const float* __restrict__ x,
               float* __restrict__ low_out,
               float* __restrict__ high_out)
{
    // sb[W][0..5]  = head floats x[8E..8E+5]   of warp W's lane 0
    // sb[W][6..11] = tail floats x[8E+2..8E+7] of warp W's lane 31
    __shared__ float sb[NWSLOT][12];

    const float h0 = -0.010597401784997278f;
    const float h1 =  0.032883011666982945f;
    const float h2 =  0.030841381835986965f;
    const float h3 = -0.18703481171888114f;
    const float h4 = -0.02798376941698385f;
    const float h5 =  0.6308807679295904f;
    const float h6 =  0.7148465705525415f;
    const float h7 =  0.23037781330885523f;

    const int t = threadIdx.x;
    const int l = t & 31;
    const int wid = t >> 5;              // warp in CTA, 0..7
    const size_t row = blockIdx.x;
    const float* __restrict__ xr = x + row * (size_t)ROW_L;
    float* __restrict__ lowp  = low_out  + row * (size_t)ROW_L;
    float* __restrict__ highp = high_out + row * (size_t)ROW_L;

    // Front-batched main loads: 2 x LDG.256.cs (read-once stream)
    F8 va[2];
    #pragma unroll
    for (int g = 0; g < 2; ++g)
        va[g] = ldg256cs(xr + (size_t)(g * NTHREADS + t) * 8);

    // Stage warp-boundary floats for both groups, one barrier
    #pragma unroll
    for (int g = 0; g < 2; ++g) {
        const int W = g * 8 + wid;
        if (l == 0) {
            #pragma unroll
            for (int i = 0; i < 6; ++i) sb[W][i] = va[g].v[i];
        }
        if (l == 31) {
            #pragma unroll
            for (int i = 0; i < 6; ++i) sb[W][6 + i] = va[g].v[2 + i];
        }
    }
    __syncthreads();

    #pragma unroll
    for (int g = 0; g < 2; ++g) {
        const int E = g * NTHREADS + t;      // float8 index in row, 0..511
        const int W = g * 8 + wid;           // linear warp slot, 0..15
        const F8 v = va[g];

        // window w[i] = X(8E - 6 + i), i = 0..19
        float w0, w1, w2, w3, w4, w5;
        const float w6 = v.v[0], w7 = v.v[1], w8 = v.v[2], w9 = v.v[3];
        const float w10 = v.v[4], w11 = v.v[5], w12 = v.v[6], w13 = v.v[7];
        float w14, w15, w16, w17, w18, w19;

        // halos via distance-1 shuffle (full-warp convergent)
        w0  = __shfl_up_sync(0xffffffffu, v.v[2], 1);
        w1  = __shfl_up_sync(0xffffffffu, v.v[3], 1);
        w2  = __shfl_up_sync(0xffffffffu, v.v[4], 1);
        w3  = __shfl_up_sync(0xffffffffu, v.v[5], 1);
        w4  = __shfl_up_sync(0xffffffffu, v.v[6], 1);
        w5  = __shfl_up_sync(0xffffffffu, v.v[7], 1);
        w14 = __shfl_down_sync(0xffffffffu, v.v[0], 1);
        w15 = __shfl_down_sync(0xffffffffu, v.v[1], 1);
        w16 = __shfl_down_sync(0xffffffffu, v.v[2], 1);
        w17 = __shfl_down_sync(0xffffffffu, v.v[3], 1);
        w18 = __shfl_down_sync(0xffffffffu, v.v[4], 1);
        w19 = __shfl_down_sync(0xffffffffu, v.v[5], 1);

        // warp-boundary fixups: shared (interior) or own-register reflection
        if (l == 0) {
            if (W == 0) {
                // X(-6..-1) = x[5..0] = own v[5..0] reversed
                w0 = v.v[5]; w1 = v.v[4]; w2 = v.v[3];
                w3 = v.v[2]; w4 = v.v[1]; w5 = v.v[0];
            } else {
                w0 = sb[W - 1][6];  w1 = sb[W - 1][7];  w2 = sb[W - 1][8];
                w3 = sb[W - 1][9];  w4 = sb[W - 1][10]; w5 = sb[W - 1][11];
            }
        }
        if (l == 31) {
            if (W == NWSLOT - 1) {
                // X(4096..4101) = x[4095..4090] = own v[7..2] reversed
                w14 = v.v[7]; w15 = v.v[6]; w16 = v.v[5];
                w17 = v.v[4]; w18 = v.v[3]; w19 = v.v[2];
            } else {
                w14 = sb[W + 1][0]; w15 = sb[W + 1][1]; w16 = sb[W + 1][2];
                w17 = sb[W + 1][3]; w18 = sb[W + 1][4]; w19 = sb[W + 1][5];
            }
        }

        // analysis: ca[j] (global coeff index 4E + j), j = 0..6
        // ca_j = sum_m h[m] * w[2j + 7 - m]
        const float wv[20] = { w0, w1, w2, w3, w4, w5, w6, w7, w8, w9,
                               w10, w11, w12, w13, w14, w15, w16, w17, w18, w19 };
        float ca[7];
        #pragma unroll
        for (int j = 0; j < 7; ++j) {
            float s;
            s = h0 * wv[2 * j + 7];
            s = fmaf(h1, wv[2 * j + 6], s);
            s = fmaf(h2, wv[2 * j + 5], s);
            s = fmaf(h3, wv[2 * j + 4], s);
            s = fmaf(h4, wv[2 * j + 3], s);
            s = fmaf(h5, wv[2 * j + 2], s);
            s = fmaf(h6, wv[2 * j + 1], s);
            s = fmaf(h7, wv[2 * j + 0], s);
            ca[j] = s;
        }

        // synthesis: pairs p = 0..3 -> outputs x[8E .. 8E+7]
        float le[4], lo[4];
        #pragma unroll
        for (int p = 0; p < 4; ++p) {
            float e;
            e = h1 * ca[p];
            e = fmaf(h3, ca[p + 1], e);
            e = fmaf(h5, ca[p + 2], e);
            e = fmaf(h7, ca[p + 3], e);
            le[p] = e;

            float o;
            o = h0 * ca[p];
            o = fmaf(h2, ca[p + 1], o);
            o = fmaf(h4, ca[p + 2], o);
            o = fmaf(h6, ca[p + 3], o);
            lo[p] = o;
        }

        stg256(lowp + (size_t)E * 8,
               le[0], lo[0], le[1], lo[1], le[2], lo[2], le[3], lo[3]);
        stg256(highp + (size_t)E * 8,
               w6 - le[0], w7 - lo[0], w8 - le[1], w9 - lo[1],
               w10 - le[2], w11 - lo[2], w12 - le[3], w13 - lo[3]);
    }
}

extern "C" void kernel_launch(void* const* d_in, const int* in_sizes, int n_in,
                              void* d_out, int out_size)
{
    const float* x = (const float*)d_in[0];
    const int n = in_sizes[0];            // 16*512*4096
    float* low  = (float*)d_out;          // outputs concatenated: (low, high)
    float* high = low + (size_t)n;
    const int rows = n / ROW_L;           // 8192
    dwt_db4_kernel<<<rows, NTHREADS>>>(x, low, high);
}